// round 14
// baseline (speedup 1.0000x reference)
#include <cuda_runtime.h>
#include <cuda_bf16.h>
#include <cstdint>

#define C_IN   4096
#define BATCH  8192
#define C_OUT  4096
#define ROW_SPLIT 32

// ---------------------------------------------------------------------------
// Device-global scratch — small (~1.1 MB).
// ---------------------------------------------------------------------------
__device__ float g_noise[C_IN];
__device__ float g_a[C_IN];
__device__ float g_d[C_IN];
__device__ float g_psum[ROW_SPLIT * C_IN];
__device__ float g_psq [ROW_SPLIT * C_IN];

// ---------------------------------------------------------------------------
// Helpers
// ---------------------------------------------------------------------------
__device__ __forceinline__ uint32_t smem_u32(const void* p) {
    uint32_t a;
    asm("{ .reg .u64 t; cvta.to.shared.u64 t, %1; cvt.u32.u64 %0, t; }" : "=r"(a) : "l"(p));
    return a;
}
__device__ __forceinline__ void ldsm_x4(uint32_t addr, uint32_t& r0, uint32_t& r1,
                                        uint32_t& r2, uint32_t& r3) {
    asm volatile("ldmatrix.sync.aligned.m8n8.x4.shared.b16 {%0,%1,%2,%3}, [%4];"
                 : "=r"(r0), "=r"(r1), "=r"(r2), "=r"(r3) : "r"(addr));
}
__device__ __forceinline__ void mma16816(float& c0, float& c1, float& c2, float& c3,
                                         uint32_t a0, uint32_t a1, uint32_t a2, uint32_t a3,
                                         uint32_t b0, uint32_t b1) {
    asm volatile(
        "mma.sync.aligned.m16n8k16.row.col.f32.bf16.bf16.f32 "
        "{%0,%1,%2,%3}, {%4,%5,%6,%7}, {%8,%9}, {%0,%1,%2,%3};"
        : "+f"(c0), "+f"(c1), "+f"(c2), "+f"(c3)
        : "r"(a0), "r"(a1), "r"(a2), "r"(a3), "r"(b0), "r"(b1));
}
__device__ __forceinline__ uint32_t pack_bf16(float lo, float hi) {
    __nv_bfloat162 v = {__float2bfloat16(lo), __float2bfloat16(hi)};
    return *(const uint32_t*)&v;
}

// ---------------------------------------------------------------------------
// Kernel 1: PoolRandom noise (LCG jump-ahead prefill + serial pool chase).
// ---------------------------------------------------------------------------
__global__ void noise_kernel() {
    __shared__ unsigned seq[2 * C_IN];
    __shared__ unsigned outv[C_IN];
    const int tid = threadIdx.x;

    {
        unsigned e = (unsigned)(tid * 32 + 1);
        unsigned ra = 1u, rc = 0u;
        unsigned ba = 65539u, bc = 1u;
        while (e) {
            if (e & 1u) { rc = ba * rc + bc; ra = ba * ra; }
            bc = ba * bc + bc;
            ba = ba * ba;
            e >>= 1u;
        }
        unsigned s = ra * 123u + rc;
        seq[tid * 32] = s;
        #pragma unroll
        for (int i = 1; i < 32; i++) { s = 65539u * s + 1u; seq[tid * 32 + i] = s; }
    }
    __syncthreads();

    if (tid == 0) {
        int nxt = C_IN - 1;
        #pragma unroll 1
        for (int i = 0; i < C_IN; i++) {
            nxt = (int)(seq[nxt] & (unsigned)(C_IN - 1));
            outv[i] = seq[nxt];
            seq[nxt] = seq[C_IN + i];
        }
    }
    __syncthreads();

    for (int i = tid; i < C_IN; i += 256)
        g_noise[i] = (float)((double)outv[i] * 1e-9);
}

// ---------------------------------------------------------------------------
// Kernel 2: per-channel partial sum / sumsq of h = relu(x + noise).
// ---------------------------------------------------------------------------
__global__ void stats_kernel(const float* __restrict__ x) {
    const int col = blockIdx.x * 256 + threadIdx.x;
    const int r0  = blockIdx.y * (BATCH / ROW_SPLIT);
    const float nz = g_noise[col];
    float s = 0.f, q = 0.f;
    const float* p = x + (size_t)r0 * C_IN + col;
    #pragma unroll 4
    for (int r = 0; r < BATCH / ROW_SPLIT; r++) {
        float h = fmaxf(p[(size_t)r * C_IN] + nz, 0.f);
        s += h; q += h * h;
    }
    g_psum[blockIdx.y * C_IN + col] = s;
    g_psq [blockIdx.y * C_IN + col] = q;
}

// ---------------------------------------------------------------------------
// Kernel 3: reduce partials -> BN fold:  hn = h*a + d
// ---------------------------------------------------------------------------
__global__ void finalize_kernel(const float* __restrict__ gamma,
                                const float* __restrict__ beta) {
    const int c = blockIdx.x * 256 + threadIdx.x;
    float s = 0.f, q = 0.f;
    #pragma unroll
    for (int i = 0; i < ROW_SPLIT; i++) { s += g_psum[i * C_IN + c]; q += g_psq[i * C_IN + c]; }
    const float mean = s * (1.f / BATCH);
    const float var  = q * (1.f / BATCH) - mean * mean;
    const float a = rsqrtf(var + 0.8f) * gamma[c];
    g_a[c] = a;
    g_d[c] = beta[c] - mean * a;
}

// ---------------------------------------------------------------------------
// Kernel 4: fused GEMM, 512 threads / 16 warps, warp tile 32x32.
//   Double-buffered smem (48KB static), 1 barrier/chunk,
//   mma(buf[c%2]) overlaps convert(c+1 -> buf[(c+1)%2]).
//   3-term bf16 split, term-major MMA emission for ILP.
// ---------------------------------------------------------------------------
#define GBM 128
#define GBN 128
#define GBK 16
#define NTHREADS 512
#define NCHUNK (C_IN / GBK)             // 256
#define PITCH 48
#define BF_TILE (128 * PITCH)            // 6144
#define AHI_OFF 0
#define ALO_OFF (1 * BF_TILE)
#define BHI_OFF (2 * BF_TILE)
#define BLO_OFF (3 * BF_TILE)
#define BF_BUF (4 * BF_TILE)             // 24576
#define SMEM_TOT (2 * BF_BUF)            // 49152 = 48KB

// 512 threads: thread t owns (row = t>>2, quarter = t&3) -> one float4 per operand.
__device__ __forceinline__ void load_regs(float4& xr, float4& wr,
                                          const float* __restrict__ x,
                                          const float* __restrict__ W,
                                          int c, int tid, int rowBase, int colBase) {
    const int k0 = c * GBK;
    const int row = tid >> 2, q = tid & 3;
    xr = *(const float4*)(x + (size_t)(rowBase + row) * C_IN + k0 + q * 4);
    wr = *(const float4*)(W + (size_t)(colBase + row) * C_IN + k0 + q * 4);
}

__device__ __forceinline__ void convert_phase(uint32_t bbase, float4 xv, float4 wv,
                                              int c, int tid) {
    const int row = tid >> 2, q = tid & 3;
    const int k = c * GBK + q * 4;
    const uint32_t dst = bbase + row * PITCH + q * 8;

    // A: hn = relu(x+noise)*a + d -> 4 bf16 hi + 4 bf16 lo
    const float4 nz = *(const float4*)(g_noise + k);
    const float4 av = *(const float4*)(g_a + k);
    const float4 dv = *(const float4*)(g_d + k);
    float h0 = fmaxf(xv.x + nz.x, 0.f) * av.x + dv.x;
    float h1 = fmaxf(xv.y + nz.y, 0.f) * av.y + dv.y;
    float h2 = fmaxf(xv.z + nz.z, 0.f) * av.z + dv.z;
    float h3 = fmaxf(xv.w + nz.w, 0.f) * av.w + dv.w;
    __nv_bfloat16 e0 = __float2bfloat16(h0), e1 = __float2bfloat16(h1);
    __nv_bfloat16 e2 = __float2bfloat16(h2), e3 = __float2bfloat16(h3);
    __nv_bfloat162 hp01 = {e0, e1}, hp23 = {e2, e3};
    uint32_t hi0 = *(const uint32_t*)&hp01, hi1 = *(const uint32_t*)&hp23;
    uint32_t lo0 = pack_bf16(h0 - __bfloat162float(e0), h1 - __bfloat162float(e1));
    uint32_t lo1 = pack_bf16(h2 - __bfloat162float(e2), h3 - __bfloat162float(e3));
    asm volatile("st.shared.v2.b32 [%0], {%1,%2};" ::
        "r"(dst + AHI_OFF), "r"(hi0), "r"(hi1) : "memory");
    asm volatile("st.shared.v2.b32 [%0], {%1,%2};" ::
        "r"(dst + ALO_OFF), "r"(lo0), "r"(lo1) : "memory");

    // B: W split -> 4 bf16 hi + 4 bf16 lo
    __nv_bfloat16 f0 = __float2bfloat16(wv.x), f1 = __float2bfloat16(wv.y);
    __nv_bfloat16 f2 = __float2bfloat16(wv.z), f3 = __float2bfloat16(wv.w);
    __nv_bfloat162 wp01 = {f0, f1}, wp23 = {f2, f3};
    uint32_t whi0 = *(const uint32_t*)&wp01, whi1 = *(const uint32_t*)&wp23;
    uint32_t wlo0 = pack_bf16(wv.x - __bfloat162float(f0), wv.y - __bfloat162float(f1));
    uint32_t wlo1 = pack_bf16(wv.z - __bfloat162float(f2), wv.w - __bfloat162float(f3));
    asm volatile("st.shared.v2.b32 [%0], {%1,%2};" ::
        "r"(dst + BHI_OFF), "r"(whi0), "r"(whi1) : "memory");
    asm volatile("st.shared.v2.b32 [%0], {%1,%2};" ::
        "r"(dst + BLO_OFF), "r"(wlo0), "r"(wlo1) : "memory");
}

__device__ __forceinline__ void mma_phase(uint32_t bbase, float (&acc)[2][4][4],
                                          int warpARow, int warpBRow,
                                          int aRowSel, int aKByte,
                                          int bRowSel, int bKByte) {
    // Load all fragments first (8 ldsm), then emit term-major MMAs.
    uint32_t ahi[2][4], alo[2][4], bhi[4][2], blo[4][2];
    #pragma unroll
    for (int mt = 0; mt < 2; mt++) {
        const uint32_t aoff = (uint32_t)((warpARow + mt * 16 + aRowSel) * PITCH + aKByte);
        ldsm_x4(bbase + AHI_OFF + aoff, ahi[mt][0], ahi[mt][1], ahi[mt][2], ahi[mt][3]);
        ldsm_x4(bbase + ALO_OFF + aoff, alo[mt][0], alo[mt][1], alo[mt][2], alo[mt][3]);
    }
    #pragma unroll
    for (int bt = 0; bt < 2; bt++) {
        const uint32_t boff = (uint32_t)((warpBRow + bt * 16 + bRowSel) * PITCH + bKByte);
        uint32_t r0, r1, r2, r3;
        ldsm_x4(bbase + BHI_OFF + boff, r0, r1, r2, r3);
        bhi[bt * 2][0] = r0; bhi[bt * 2][1] = r1;
        bhi[bt * 2 + 1][0] = r2; bhi[bt * 2 + 1][1] = r3;
        ldsm_x4(bbase + BLO_OFF + boff, r0, r1, r2, r3);
        blo[bt * 2][0] = r0; blo[bt * 2][1] = r1;
        blo[bt * 2 + 1][0] = r2; blo[bt * 2 + 1][1] = r3;
    }
    // term 1: Ahi*Bhi  (8 independent MMAs)
    #pragma unroll
    for (int mt = 0; mt < 2; mt++)
        #pragma unroll
        for (int nt = 0; nt < 4; nt++)
            mma16816(acc[mt][nt][0], acc[mt][nt][1], acc[mt][nt][2], acc[mt][nt][3],
                     ahi[mt][0], ahi[mt][1], ahi[mt][2], ahi[mt][3],
                     bhi[nt][0], bhi[nt][1]);
    // term 2: Ahi*Blo
    #pragma unroll
    for (int mt = 0; mt < 2; mt++)
        #pragma unroll
        for (int nt = 0; nt < 4; nt++)
            mma16816(acc[mt][nt][0], acc[mt][nt][1], acc[mt][nt][2], acc[mt][nt][3],
                     ahi[mt][0], ahi[mt][1], ahi[mt][2], ahi[mt][3],
                     blo[nt][0], blo[nt][1]);
    // term 3: Alo*Bhi
    #pragma unroll
    for (int mt = 0; mt < 2; mt++)
        #pragma unroll
        for (int nt = 0; nt < 4; nt++)
            mma16816(acc[mt][nt][0], acc[mt][nt][1], acc[mt][nt][2], acc[mt][nt][3],
                     alo[mt][0], alo[mt][1], alo[mt][2], alo[mt][3],
                     bhi[nt][0], bhi[nt][1]);
}

__global__ void __launch_bounds__(NTHREADS)
gemm_mma_kernel(const float* __restrict__ x, const float* __restrict__ W,
                const float* __restrict__ bias, float* __restrict__ out) {
    __shared__ __align__(128) unsigned char smem[SMEM_TOT];
    const uint32_t sb = smem_u32(smem);
    const uint32_t buf0 = sb, buf1 = sb + BF_BUF;
    const int tid = threadIdx.x;
    const int wid = tid >> 5, lane = tid & 31;
    const int rowBase = blockIdx.y * GBM;
    const int colBase = blockIdx.x * GBN;

    // 16 warps: 4 warp-rows (M) x 4 warp-cols (N), warp tile 32x32
    const int warpARow = (wid & 3) * 32;
    const int warpBRow = (wid >> 2) * 32;

    const int aRowSel = lane & 15;
    const int aKByte  = (lane >> 4) << 4;
    const int bRowSel = (lane & 7) + ((lane >> 4) << 3);
    const int bKByte  = ((lane >> 3) & 1) << 4;

    float acc[2][4][4];
    #pragma unroll
    for (int i = 0; i < 2; i++)
        #pragma unroll
        for (int j = 0; j < 4; j++)
            #pragma unroll
            for (int e = 0; e < 4; e++) acc[i][j][e] = 0.f;

    float4 xr0, wr0, xr1, wr1;
    load_regs(xr0, wr0, x, W, 0, tid, rowBase, colBase);
    convert_phase(buf0, xr0, wr0, 0, tid);
    load_regs(xr1, wr1, x, W, 1, tid, rowBase, colBase);
    __syncthreads();

    #pragma unroll 1
    for (int c = 0; c < NCHUNK; c += 2) {
        // iter c: mma(buf0) || convert(c+1 -> buf1); prefetch c+2
        if (c + 2 < NCHUNK) load_regs(xr0, wr0, x, W, c + 2, tid, rowBase, colBase);
        convert_phase(buf1, xr1, wr1, c + 1, tid);
        mma_phase(buf0, acc, warpARow, warpBRow, aRowSel, aKByte, bRowSel, bKByte);
        __syncthreads();
        // iter c+1: mma(buf1) || convert(c+2 -> buf0); prefetch c+3
        if (c + 3 < NCHUNK) load_regs(xr1, wr1, x, W, c + 3, tid, rowBase, colBase);
        if (c + 2 < NCHUNK) convert_phase(buf0, xr0, wr0, c + 2, tid);
        mma_phase(buf1, acc, warpARow, warpBRow, aRowSel, aKByte, bRowSel, bKByte);
        __syncthreads();
    }

    // Epilogue
    const int lr = lane >> 2;
    const int lc = (lane & 3) * 2;
    #pragma unroll
    for (int nt = 0; nt < 4; nt++) {
        const int col = colBase + warpBRow + nt * 8 + lc;
        const float bv0 = bias[col];
        const float bv1 = bias[col + 1];
        #pragma unroll
        for (int mt = 0; mt < 2; mt++) {
            const int row0 = rowBase + warpARow + mt * 16 + lr;
            float2 v0 = { acc[mt][nt][0] + bv0, acc[mt][nt][1] + bv1 };
            float2 v1 = { acc[mt][nt][2] + bv0, acc[mt][nt][3] + bv1 };
            *(float2*)(out + (size_t)row0 * C_OUT + col)       = v0;
            *(float2*)(out + (size_t)(row0 + 8) * C_OUT + col) = v1;
        }
    }
}

// ---------------------------------------------------------------------------
// Launch — kernel launches only.
// ---------------------------------------------------------------------------
extern "C" void kernel_launch(void* const* d_in, const int* in_sizes, int n_in,
                              void* d_out, int out_size) {
    const float* x     = (const float*)d_in[0];
    const float* gamma = (const float*)d_in[1];
    const float* beta  = (const float*)d_in[2];
    const float* W     = (const float*)d_in[3];
    const float* b     = (const float*)d_in[4];
    float* out = (float*)d_out;

    noise_kernel<<<1, 256>>>();
    stats_kernel<<<dim3(C_IN / 256, ROW_SPLIT), 256>>>(x);
    finalize_kernel<<<C_IN / 256, 256>>>(gamma, beta);
    gemm_mma_kernel<<<dim3(C_OUT / GBN, BATCH / GBM), NTHREADS>>>(x, W, b, out);
}